// round 3
// baseline (speedup 1.0000x reference)
#include <cuda_runtime.h>

#define NB        256            // bins per batch
#define TB        512            // bucket-table size
#define BLOCK     512            // threads per block
#define BPB       74             // blocks per batch: 4*74=296 = 2 blocks/SM
#define MAXB      8
#define NGAP      (NB + 1)
#define GAPSTRIDE 8              // 32B per gap slot -> spread L2 atomic lines

// Static zero-init scratch; final block re-zeros each launch (graph-replay safe).
__device__ unsigned g_gapmax [MAXB * NGAP * GAPSTRIDE];  // max of float bits (pv>0)
__device__ unsigned g_gapminN[MAXB * NGAP * GAPSTRIDE];  // max of ~bits == ~(min bits)
__device__ float    g_sorted[MAXB * NB];
__device__ float    g_psum[MAXB * BPB];
__device__ float    g_pcnt[MAXB * BPB];
__device__ unsigned g_arrive;

__device__ __forceinline__ unsigned vldu(const unsigned* p) { return *(const volatile unsigned*)p; }
__device__ __forceinline__ float    vldf(const float* p)    { return *(const volatile float*)p; }

// per-point: table-accelerated nearest-bin (dir 1) + shared gap tally (dir 2)
__device__ __forceinline__ void process_point(
    float pv, const float* __restrict__ sc, const unsigned* __restrict__ P,
    float lo, float scale,
    unsigned* smax, unsigned* sminN,
    float& sumA, float& cnt)
{
    int k = (int)floorf((pv - lo) * scale);
    k = min(TB - 1, max(k, 0));
    unsigned pr = P[k];
    int a = (int)(pr & 0xffffu), b = (int)(pr >> 16);
    while (a < b) {                       // usually 0-1 iterations
        int m = (a + b) >> 1;
        if (sc[m] <= pv) a = m + 1; else b = m;
    }
    int g = a;                            // #bins <= pv, in [0,256]
    float dlo = (g > 0)  ? (pv - sc[g - 1]) : 3e18f;
    float dhi = (g < NB) ? (sc[g] - pv)     : 3e18f;

    if (pv >= 0.001f) {                   // same mask constant as reference
        sumA += fminf(dlo * dlo, dhi * dhi);
        cnt  += 1.0f;
        unsigned pb = __float_as_uint(pv);        // pv>0: uint order == float order
        if (pb > smax[g])    atomicMax(&smax[g],  pb);   // monotonic -> stale-skip safe
        unsigned nb = ~pb;
        if (nb > sminN[g])   atomicMax(&sminN[g], nb);
    }
}

__global__ void __launch_bounds__(BLOCK)
k_all(const float* __restrict__ bins, const float* __restrict__ pts,
      int V, int B, float* __restrict__ out)
{
    __shared__ float          sc[NB];
    __shared__ unsigned short kb[NB];          // bucket of each sorted bin
    __shared__ unsigned short Gt[TB + 1];      // #bins in buckets < k
    __shared__ unsigned       P[TB];           // packed (G[k], G[k+1])
    __shared__ unsigned       smax[NGAP], sminN[NGAP];
    __shared__ float          red[16], red2[16];
    __shared__ float          s_above[NB];
    __shared__ float          sh_n[MAXB], sh_sA[MAXB];
    __shared__ float          s_lo, s_scale;
    __shared__ int            s_last;

    const int b = blockIdx.y, t = threadIdx.x;
    const int lane = t & 31, w = t >> 5;

    // ---- load bins + init gap tallies ---------------------------------------
    if (t < NB) {
        sc[t] = bins[b * NB + t];
        smax[t] = 0u; sminN[t] = 0u;
    }
    if (t == 0) { smax[NB] = 0u; sminN[NB] = 0u; }
    __syncthreads();

    // ---- bitonic sort of 256 bins (threads 0..255 active) -------------------
    for (int k = 2; k <= NB; k <<= 1) {
        for (int j = k >> 1; j > 0; j >>= 1) {
            if (t < NB) {
                int ixj = t ^ j;
                if (ixj > t) {
                    float a = sc[t], c = sc[ixj];
                    bool up = ((t & k) == 0);
                    if ((a > c) == up) { sc[t] = c; sc[ixj] = a; }
                }
            }
            __syncthreads();
        }
    }

    // ---- bucket table build --------------------------------------------------
    if (t == 0) {
        float lo = sc[0], hi = sc[NB - 1];
        float d = hi - lo;
        s_lo = lo;
        s_scale = (d > 1e-30f) ? ((float)TB / d) : 0.0f;
    }
    __syncthreads();
    const float lo = s_lo, scale = s_scale;
    if (t < NB) {
        int kbin = (int)floorf((sc[t] - lo) * scale);
        kb[t] = (unsigned short)min(TB - 1, max(kbin, 0));
    }
    __syncthreads();
    for (int k = t; k <= TB; k += BLOCK) {       // Gt[k] = #bins with bucket < k
        int g = 0;
#pragma unroll
        for (int s2 = NB; s2; s2 >>= 1) {
            int nt = g + s2;
            if (nt <= NB && (int)kb[nt - 1] < k) g = nt;
        }
        Gt[k] = (unsigned short)g;
    }
    __syncthreads();
    for (int k = t; k < TB; k += BLOCK)
        P[k] = (unsigned)Gt[k] | ((unsigned)Gt[k + 1] << 16);
    __syncthreads();

    // ---- main pass over this block's slice of depth points -------------------
    const float* p = pts + (size_t)b * V;
    float sumA = 0.0f, cnt = 0.0f;
    const int V4 = V >> 2;
    const float4* p4 = reinterpret_cast<const float4*>(p);
    for (int i = blockIdx.x * BLOCK + t; i < V4; i += BPB * BLOCK) {
        float4 q = p4[i];
        process_point(q.x, sc, P, lo, scale, smax, sminN, sumA, cnt);
        process_point(q.y, sc, P, lo, scale, smax, sminN, sumA, cnt);
        process_point(q.z, sc, P, lo, scale, smax, sminN, sumA, cnt);
        process_point(q.w, sc, P, lo, scale, smax, sminN, sumA, cnt);
    }
    if (blockIdx.x == 0 && t < (V & 3))
        process_point(p[(V & ~3) + t], sc, P, lo, scale, smax, sminN, sumA, cnt);

    // ---- deterministic block reduction of sumA / cnt -------------------------
#pragma unroll
    for (int o = 16; o; o >>= 1) {
        sumA += __shfl_down_sync(0xffffffffu, sumA, o);
        cnt  += __shfl_down_sync(0xffffffffu, cnt,  o);
    }
    if (lane == 0) { red[w] = sumA; red2[w] = cnt; }
    __syncthreads();
    if (t == 0) {
        float s = 0.0f, c = 0.0f;
        for (int i = 0; i < 16; i++) { s += red[i]; c += red2[i]; }
        g_psum[b * BPB + blockIdx.x] = s;
        g_pcnt[b * BPB + blockIdx.x] = c;
    }

    // ---- flush shared gap tallies to padded global slots ----------------------
    __syncthreads();                               // all shared atomics done
    for (int i = t; i < NGAP; i += BLOCK) {
        unsigned m = smax[i];
        if (m)  atomicMax(&g_gapmax [(b * NGAP + i) * GAPSTRIDE], m);
        unsigned n2 = sminN[i];
        if (n2) atomicMax(&g_gapminN[(b * NGAP + i) * GAPSTRIDE], n2);
    }
    if (blockIdx.x == 0 && t < NB) g_sorted[b * NB + t] = sc[t];

    // ---- arrival: last block finalizes ----------------------------------------
    __threadfence();
    __syncthreads();
    if (t == 0) {
        unsigned total = gridDim.x * gridDim.y;
        unsigned old = atomicAdd(&g_arrive, 1u);
        s_last = (old == total - 1u) ? 1 : 0;
    }
    __syncthreads();
    if (!s_last) return;
    __threadfence();                               // acquire side

    // ======================= FINALIZE (one block, 512 thr) =====================
    for (int bb = 0; bb < B; bb++) {
        float s = 0.0f, c = 0.0f;
        if (t < BPB) { s = vldf(&g_psum[bb * BPB + t]); c = vldf(&g_pcnt[bb * BPB + t]); }
#pragma unroll
        for (int o = 16; o; o >>= 1) {
            s += __shfl_down_sync(0xffffffffu, s, o);
            c += __shfl_down_sync(0xffffffffu, c, o);
        }
        if (lane == 0) { red[w] = s; red2[w] = c; }
        __syncthreads();
        if (t == 0) {
            float ss = 0.0f, cc = 0.0f;
            for (int i = 0; i < 16; i++) { ss += red[i]; cc += red2[i]; }
            sh_sA[bb] = ss; sh_n[bb] = cc;
        }
        __syncthreads();
    }

    float Lmax = 0.0f;
    for (int bb = 0; bb < B; bb++) Lmax = fmaxf(Lmax, sh_n[bb]);

    float total_loss = 0.0f;   // meaningful in thread 0 only
    for (int bb = 0; bb < B; bb++) {
        float c  = (t < NB) ? vldf(&g_sorted[bb * NB + t]) : 3e18f;
        float c2 = (t < NB) ? c * c : 3e18f;

        // min over bins of c^2 (warps 8-15 contribute +big)
        float m = c2;
#pragma unroll
        for (int o = 16; o; o >>= 1) m = fminf(m, __shfl_down_sync(0xffffffffu, m, o));
        if (lane == 0) red[w] = m;
        __syncthreads();
        float minc2 = red[0];
        for (int i = 1; i < 16; i++) minc2 = fminf(minc2, red[i]);
        __syncthreads();

        // nearest valid point BELOW bin t: prefix-max of gap maxes 0..t (t<256)
        unsigned mb = (t < NB) ? vldu(&g_gapmax[(bb * NGAP + t) * GAPSTRIDE]) : 0u;
        float below = (mb == 0u) ? -3e18f : __uint_as_float(mb);
#pragma unroll
        for (int o = 1; o < 32; o <<= 1) {
            float u = __shfl_up_sync(0xffffffffu, below, o);
            if (lane >= o) below = fmaxf(below, u);
        }
        if (lane == 31 && w < 8) red2[w] = below;
        __syncthreads();
        float carry = -3e18f;
        for (int i = 0; i < w && i < 8; i++) carry = fmaxf(carry, red2[i]);
        below = fmaxf(below, carry);
        __syncthreads();

        // nearest valid point ABOVE bin j: suffix-min of gap mins j+1..256.
        // thread t (<256) loads gap (256 - t); prefix-min; bin j reads slot 255-j.
        unsigned na = (t < NB) ? vldu(&g_gapminN[(bb * NGAP + (NB - t)) * GAPSTRIDE]) : 0u;
        float above = (na == 0u) ? 3e18f : __uint_as_float(~na);
#pragma unroll
        for (int o = 1; o < 32; o <<= 1) {
            float u = __shfl_up_sync(0xffffffffu, above, o);
            if (lane >= o) above = fminf(above, u);
        }
        if (lane == 31 && w < 8) red2[w] = above;
        __syncthreads();
        float carry2 = 3e18f;
        for (int i = 0; i < w && i < 8; i++) carry2 = fminf(carry2, red2[i]);
        above = fminf(above, carry2);
        if (t < NB) s_above[t] = above;
        __syncthreads();

        float mv = 0.0f;
        float npad = Lmax - sh_n[bb];
        if (t < NB) {
            float ab = s_above[NB - 1 - t];
            float d1 = c - below;          // sentinels -> ~9e36, never the min
            float d2 = ab - c;
            mv = fminf(d1 * d1, d2 * d2);
            if (npad > 0.0f) mv = fminf(mv, c2);   // zero pad-point candidate
        }
#pragma unroll
        for (int o = 16; o; o >>= 1) mv += __shfl_down_sync(0xffffffffu, mv, o);
        if (lane == 0) red[w] = mv;
        __syncthreads();
        if (t == 0) {
            float sB = 0.0f;
            for (int i = 0; i < 16; i++) sB += red[i];
            total_loss += sh_sA[bb] + npad * minc2 + sB;
        }
        __syncthreads();
    }
    if (t == 0) out[0] = total_loss / (float)B;

    // ---- reset scratch for next graph replay ----------------------------------
    __syncthreads();   // all reads above complete
    for (int i = t; i < MAXB * NGAP; i += BLOCK) {
        g_gapmax [i * GAPSTRIDE] = 0u;
        g_gapminN[i * GAPSTRIDE] = 0u;
    }
    if (t == 0) g_arrive = 0u;
}

// -----------------------------------------------------------------------------
extern "C" void kernel_launch(void* const* d_in, const int* in_sizes, int n_in,
                              void* d_out, int out_size)
{
    const float* bins = (const float*)d_in[0];
    const float* pts  = (const float*)d_in[1];
    int sb = in_sizes[0], sp = in_sizes[1];
    if (sb > sp) {                 // defensive: detect swapped input order
        const float* tmp = bins; bins = pts; pts = tmp;
        int ts = sb; sb = sp; sp = ts;
    }
    int B = sb / NB;               // 4
    int V = sp / B;                // 157696

    dim3 grid(BPB, B);
    k_all<<<grid, BLOCK>>>(bins, pts, V, B, (float*)d_out);
}